// round 16
// baseline (speedup 1.0000x reference)
#include <cuda_runtime.h>
#include <cuda_fp16.h>
#include <cstdint>

#define LQ   4096
#define CDIM 256
#define NB   2
#define NH   8
#define MTOT 8192

// ---------------- scratch ----------------
__device__ __half g_qin_h [MTOT*CDIM];   // transposed src, fp16
__device__ __half g_kvin_h[MTOT*CDIM];   // gathered kv, fp16
__device__ __half g_qh    [MTOT*CDIM];   // Q fp16 (pre-scaled by 1/sqrt(d)*log2e)
__device__ __half g_kh    [MTOT*CDIM];   // K fp16 row-major
__device__ __half g_vt    [NB*CDIM*LQ];  // V fp16 transposed [b][c][kv]
__device__ __half g_o0    [MTOT*CDIM];   // unnormalized attention out fp16, split 0
__device__ __half g_o1    [MTOT*CDIM];   // split 1
__device__ __half g_oh    [MTOT*CDIM];   // merged+normalized attention out fp16
__device__ float  g_l     [2*NB*NH*LQ];  // softmax denominators [s][b][h][row]
__device__ __half g_Wh    [4*CDIM*CDIM]; // fp16 weights: q,k,v,o

// ---------------- helpers ----------------
__device__ __forceinline__ unsigned packhf(float lo, float hi) {
    unsigned d;
    asm("cvt.rn.f16x2.f32 %0, %1, %2;" : "=r"(d) : "f"(hi), "f"(lo));
    return d;
}
__device__ __forceinline__ unsigned h2ex2(unsigned x) {
    unsigned d;
    asm("ex2.approx.f16x2 %0, %1;" : "=r"(d) : "r"(x));
    return d;
}
__device__ __forceinline__ void mma_fp16(float c[4],
                                         unsigned a0, unsigned a1, unsigned a2, unsigned a3,
                                         unsigned b0, unsigned b1) {
    asm volatile(
        "mma.sync.aligned.m16n8k16.row.col.f32.f16.f16.f32 "
        "{%0,%1,%2,%3},{%4,%5,%6,%7},{%8,%9},{%0,%1,%2,%3};"
        : "+f"(c[0]), "+f"(c[1]), "+f"(c[2]), "+f"(c[3])
        : "r"(a0), "r"(a1), "r"(a2), "r"(a3), "r"(b0), "r"(b1));
}
__device__ __forceinline__ void ldsm4(unsigned& r0, unsigned& r1, unsigned& r2, unsigned& r3,
                                      unsigned addr) {
    asm volatile("ldmatrix.sync.aligned.m8n8.x4.shared.b16 {%0,%1,%2,%3}, [%4];"
                 : "=r"(r0), "=r"(r1), "=r"(r2), "=r"(r3) : "r"(addr));
}
__device__ __forceinline__ void cpa16(void* s, const void* g) {
    unsigned sa = (unsigned)__cvta_generic_to_shared(s);
    asm volatile("cp.async.cg.shared.global [%0], [%1], 16;" :: "r"(sa), "l"(g));
}

// ---------------- 0) merged prep: transpose src + gather kv + weight convert ----------------
__global__ void prep_kernel(const float* __restrict__ src, const float* __restrict__ feat,
                            const float* __restrict__ wq, const float* __restrict__ wk,
                            const float* __restrict__ wv, const float* __restrict__ wo) {
    __shared__ float tile[32][33];
    int bid = blockIdx.x;
    int tid = threadIdx.x;
    if (bid < 2048) {
        int x = tid & 31, y = tid >> 5;
        int l0 = (bid & 127) * 32;
        int c0 = ((bid >> 7) & 7) * 32;
        int b  = bid >> 10;
#pragma unroll
        for (int i = 0; i < 4; i++) {
            int c = c0 + y + i * 8;
            tile[y + i * 8][x] = src[((size_t)(b * CDIM + c) << 12) + (l0 + x)];
        }
        __syncthreads();
#pragma unroll
        for (int i = 0; i < 4; i++) {
            int l = l0 + y + i * 8;
            g_qin_h[((size_t)(b * LQ + l)) * CDIM + c0 + x] = __float2half(tile[x][y + i * 8]);
        }
    } else if (bid < 2048 + 8192) {
        int idx = (bid - 2048) * 256 + tid;
        int j = idx & 255;
        int l = (idx >> 8) & 4095;
        int b = idx >> 20;
        int c = j / 9;
        int k = j - c * 9;
        int kh = k / 3;
        int kw = k - kh * 3;
        int oh = l >> 6, ow = l & 63;
        int fh = 2 * oh + kh - 1;
        int fw = 2 * ow + kw - 1;
        float val = 0.f;
        if ((unsigned)fh < 128u && (unsigned)fw < 128u)
            val = feat[(((size_t)(b * CDIM + c)) << 14) + (fh << 7) + fw];
        g_kvin_h[idx] = __float2half(val);
    } else {
        int t = (bid - 2048 - 8192) * 256 + tid;
        int idx4 = t * 4;
        int m = idx4 >> 16;
        const float* s = (m == 0) ? wq : (m == 1) ? wk : (m == 2) ? wv : wo;
        float4 v = *(const float4*)(s + (idx4 & 65535));
        uint2 p;
        p.x = packhf(v.x, v.y);
        p.y = packhf(v.z, v.w);
        *(uint2*)(g_Wh + idx4) = p;
    }
}

// ---------------- BM=128 x BN=64 x BK=64 fp16 GEMM, 256 thr, single-barrier pipeline ----------------
#define ASTR 36
#define QS (0.17677669529663687f * 1.4426950408889634f)
#define GD_A0 0
#define GD_A1 (128 * ASTR)
#define GD_W0 (2 * 128 * ASTR)
#define GD_W1 (2 * 128 * ASTR + 64 * ASTR)
#define GDSMEM ((2 * 128 + 2 * 64) * ASTR * 4)

extern __shared__ unsigned dynsm[];

struct GemmCtx {
    int wm, wn, g, t4;
    int ar, ah;
    int wr, wq;
};

__device__ __forceinline__ void gemm_mainloop(GemmCtx& c, const __half* A, const __half* Wh,
                                              int m0, int n0, float acc[2][4][4]) {
    const uint4* Ag = (const uint4*)(A + (size_t)(m0 + c.ar) * CDIM);
    const uint4* Wg = (const uint4*)(Wh + (size_t)(n0 + c.wr) * CDIM);
    unsigned* Ab[2] = { dynsm + GD_A0, dynsm + GD_A1 };
    unsigned* Wb[2] = { dynsm + GD_W0, dynsm + GD_W1 };
#define G_ISSUE(KT) do {                                                        \
        int bf_ = (KT) & 1;                                                     \
        _Pragma("unroll")                                                       \
        for (int i_ = 0; i_ < 4; i_++)                                          \
            cpa16(Ab[bf_] + c.ar * ASTR + (c.ah * 4 + i_) * 4, Ag + (KT) * 8 + c.ah * 4 + i_); \
        _Pragma("unroll")                                                       \
        for (int i_ = 0; i_ < 2; i_++)                                          \
            cpa16(Wb[bf_] + c.wr * ASTR + (c.wq * 2 + i_) * 4, Wg + (KT) * 8 + c.wq * 2 + i_); \
        asm volatile("cp.async.commit_group;");                                 \
    } while (0)
    G_ISSUE(0);
    for (int kt = 0; kt < 4; kt++) {
        // single in-flight group: wait tile kt, one barrier, then prefetch kt+1.
        asm volatile("cp.async.wait_group 0;");
        __syncthreads();
        if (kt < 3) G_ISSUE(kt + 1);
        const unsigned* Ah = Ab[kt & 1];
        const unsigned* Ws = Wb[kt & 1];
#pragma unroll
        for (int ks = 0; ks < 4; ks++) {
            unsigned av[2][4], bv2[4][2];
#pragma unroll
            for (int mi = 0; mi < 2; mi++) {
                int rb = (c.wm + mi * 16 + c.g) * ASTR + ks * 8;
                av[mi][0] = Ah[rb + c.t4];
                av[mi][1] = Ah[rb + 8 * ASTR + c.t4];
                av[mi][2] = Ah[rb + c.t4 + 4];
                av[mi][3] = Ah[rb + 8 * ASTR + c.t4 + 4];
            }
#pragma unroll
            for (int nj = 0; nj < 4; nj++) {
                int rb = (c.wn + nj * 8 + c.g) * ASTR + ks * 8;
                bv2[nj][0] = Ws[rb + c.t4];
                bv2[nj][1] = Ws[rb + c.t4 + 4];
            }
#pragma unroll
            for (int mi = 0; mi < 2; mi++)
#pragma unroll
                for (int nj = 0; nj < 4; nj++)
                    mma_fp16(acc[mi][nj], av[mi][0], av[mi][1], av[mi][2], av[mi][3],
                             bv2[nj][0], bv2[nj][1]);
        }
    }
    __syncthreads();   // protect smem reuse by epilogues
#undef G_ISSUE
}

__device__ __forceinline__ void gemm_init_ctx(GemmCtx& c, int tid) {
    int warp = tid >> 5, lane = tid & 31;
    c.g = lane >> 2; c.t4 = lane & 3;
    c.wm = (warp >> 1) * 32;
    c.wn = (warp & 1) * 32;
    c.ar = tid >> 1; c.ah = tid & 1;
    c.wr = tid >> 2; c.wq = tid & 3;
}

// ---------------- 1) merged Q/K/V fp16 GEMM (one launch, 768 blocks) ----------------
__global__ __launch_bounds__(256, 3) void gemm_qkv_kernel(const __half* __restrict__ Aq,
                                                          const __half* __restrict__ Akv,
                                                          const __half* __restrict__ Whall,
                                                          const float* __restrict__ bq,
                                                          const float* __restrict__ bk,
                                                          const float* __restrict__ bv) {
    int mode = blockIdx.y >> 6;
    int m0 = (blockIdx.y & 63) * 128;
    int n0 = blockIdx.x * 64;
    const __half* A = (mode == 0) ? Aq : Akv;
    const __half* Wh = Whall + mode * CDIM * CDIM;
    const float* bias = (mode == 0) ? bq : (mode == 1) ? bk : bv;

    int tid = threadIdx.x;
    GemmCtx c;
    gemm_init_ctx(c, tid);

    float acc[2][4][4] = {};
    gemm_mainloop(c, A, Wh, m0, n0, acc);

    if (mode != 2) {
        __half* Cout = (mode == 0) ? g_qh : g_kh;
        float s = (mode == 0) ? QS : 1.f;
#pragma unroll
        for (int mi = 0; mi < 2; mi++)
#pragma unroll
            for (int rs = 0; rs < 2; rs++) {
                int row = m0 + c.wm + mi * 16 + c.g + rs * 8;
#pragma unroll
                for (int nj = 0; nj < 4; nj++) {
                    int col = n0 + c.wn + nj * 8 + 2 * c.t4;
                    float v0 = acc[mi][nj][rs * 2 + 0] + bias[col];
                    float v1 = acc[mi][nj][rs * 2 + 1] + bias[col + 1];
                    *(unsigned*)(Cout + (size_t)row * CDIM + col) = packhf(v0 * s, v1 * s);
                }
            }
    } else {
        __half* Ch = (__half*)dynsm;
#pragma unroll
        for (int mi = 0; mi < 2; mi++)
#pragma unroll
            for (int rs = 0; rs < 2; rs++) {
                int rowl = c.wm + mi * 16 + c.g + rs * 8;
#pragma unroll
                for (int nj = 0; nj < 4; nj++) {
                    int coll = c.wn + nj * 8 + 2 * c.t4;
                    Ch[(coll)     * 136 + rowl] = __float2half(acc[mi][nj][rs * 2 + 0] + bias[n0 + coll]);
                    Ch[(coll + 1) * 136 + rowl] = __float2half(acc[mi][nj][rs * 2 + 1] + bias[n0 + coll + 1]);
                }
            }
        __syncthreads();
        {
            int cc = tid >> 2, qq = tid & 3;
            int b = m0 >> 12;
            int kv0 = m0 & 4095;
            uint4* dst = (uint4*)(g_vt + ((size_t)(b * CDIM + n0 + cc)) * LQ + kv0 + qq * 32);
            const uint4* s4 = (const uint4*)(Ch + cc * 136 + qq * 32);
#pragma unroll
            for (int i = 0; i < 4; i++) dst[i] = s4[i];
        }
    }
}

// ---------------- 2) flash attention: fp16, split-KV x2, one barrier per tile ----------------
#define FST 36
__global__ __launch_bounds__(256) void flash_fp16_kernel() {
    __shared__ unsigned Kt[2][64 * FST];
    __shared__ unsigned Vt[2][32 * FST];

    int qt = blockIdx.x, h = blockIdx.y;
    int b = blockIdx.z >> 1, s = blockIdx.z & 1;
    int tid = threadIdx.x;
    int w = tid >> 5, lane = tid & 31;
    int g = lane >> 2, t4 = lane & 3;
    int m0 = w * 16;
    int qbase = qt * 128;
    const unsigned ONES = 0x3C003C00u;

    unsigned qa[2][4];
    {
        const __half* Qp = g_qh + ((size_t)(b * LQ + qbase + m0)) * CDIM + h * 32;
#pragma unroll
        for (int kf = 0; kf < 2; kf++) {
            int cb = kf * 16 + 2 * t4;
            qa[kf][0] = *(const unsigned*)(Qp + (size_t)g * CDIM + cb);
            qa[kf][1] = *(const unsigned*)(Qp + (size_t)(g + 8) * CDIM + cb);
            qa[kf][2] = *(const unsigned*)(Qp + (size_t)g * CDIM + cb + 8);
            qa[kf][3] = *(const unsigned*)(Qp + (size_t)(g + 8) * CDIM + cb + 8);
        }
    }

    float oacc[4][4] = {};
    float lacc[4] = {};

    int kr = tid >> 2, kq = tid & 3;
    int vr = tid >> 3, vq = tid & 7;

    const uint4* kgp = (const uint4*)(g_kh + ((size_t)(b * LQ + kr)) * CDIM + h * 32);
    const uint4* vgp = (const uint4*)(g_vt + ((size_t)(b * CDIM + h * 32 + vr)) * LQ);
    int tbase = s * 32;

    unsigned ksh[2], vsh[2];
    ksh[0] = (unsigned)__cvta_generic_to_shared(&Kt[0][0]);
    ksh[1] = (unsigned)__cvta_generic_to_shared(&Kt[1][0]);
    vsh[0] = (unsigned)__cvta_generic_to_shared(&Vt[0][0]);
    vsh[1] = (unsigned)__cvta_generic_to_shared(&Vt[1][0]);
    unsigned koff = ((lane & 7) * FST + (lane >> 3) * 4) * 4;
    unsigned voff = koff;

#define ISSUE_TILE(T) do {                                                    \
        int buf_ = (T) & 1;                                                   \
        cpa16(&Kt[buf_][kr * FST + kq * 4], kgp + (size_t)(tbase + (T)) * 64 * (CDIM / 8) + kq); \
        cpa16(&Vt[buf_][vr * FST + vq * 4], vgp + (tbase + (T)) * 8 + vq);    \
        asm volatile("cp.async.commit_group;");                               \
    } while (0)

    ISSUE_TILE(0);

    for (int t = 0; t < 32; t++) {
        asm volatile("cp.async.wait_group 0;");
        __syncthreads();
        if (t < 31) ISSUE_TILE(t + 1);

        int buf = t & 1;
        unsigned kb = ksh[buf] + koff;
        unsigned vb = vsh[buf] + voff;

        float sacc[8][4] = {};
#pragma unroll
        for (int j = 0; j < 8; j++) {
            unsigned r0, r1, r2, r3;
            ldsm4(r0, r1, r2, r3, kb + j * (8 * FST * 4));
            mma_fp16(sacc[j], qa[0][0], qa[0][1], qa[0][2], qa[0][3], r0, r1);
            mma_fp16(sacc[j], qa[1][0], qa[1][1], qa[1][2], qa[1][3], r2, r3);
        }

        unsigned pa[4][4];
#pragma unroll
        for (int kf = 0; kf < 4; kf++) {
            int j0 = 2 * kf, j1 = 2 * kf + 1;
            pa[kf][0] = h2ex2(packhf(sacc[j0][0], sacc[j0][1]));
            pa[kf][1] = h2ex2(packhf(sacc[j0][2], sacc[j0][3]));
            pa[kf][2] = h2ex2(packhf(sacc[j1][0], sacc[j1][1]));
            pa[kf][3] = h2ex2(packhf(sacc[j1][2], sacc[j1][3]));
        }

#pragma unroll
        for (int kf = 0; kf < 4; kf++)
            mma_fp16(lacc, pa[kf][0], pa[kf][1], pa[kf][2], pa[kf][3], ONES, ONES);

#pragma unroll
        for (int nn = 0; nn < 4; nn++) {
            unsigned v0, v1, v2, v3, v4, v5, v6, v7;
            unsigned a = vb + nn * (8 * FST * 4);
            ldsm4(v0, v1, v2, v3, a);
            ldsm4(v4, v5, v6, v7, a + 64);
            mma_fp16(oacc[nn], pa[0][0], pa[0][1], pa[0][2], pa[0][3], v0, v1);
            mma_fp16(oacc[nn], pa[1][0], pa[1][1], pa[1][2], pa[1][3], v2, v3);
            mma_fp16(oacc[nn], pa[2][0], pa[2][1], pa[2][2], pa[2][3], v4, v5);
            mma_fp16(oacc[nn], pa[3][0], pa[3][1], pa[3][2], pa[3][3], v6, v7);
        }
    }
#undef ISSUE_TILE

    __half* OB = s ? g_o1 : g_o0;
    __half* op = OB + ((size_t)(b * LQ + qbase + m0)) * CDIM + h * 32;
#pragma unroll
    for (int nn = 0; nn < 4; nn++) {
        *(unsigned*)(op + (size_t)g * CDIM + nn * 8 + 2 * t4) =
            packhf(oacc[nn][0], oacc[nn][1]);
        *(unsigned*)(op + (size_t)(g + 8) * CDIM + nn * 8 + 2 * t4) =
            packhf(oacc[nn][2], oacc[nn][3]);
    }
    if (t4 == 0) {
        int row = qbase + m0 + g;
        g_l[((s * NB + b) * NH + h) * LQ + row]     = lacc[0];
        g_l[((s * NB + b) * NH + h) * LQ + row + 8] = lacc[2];
    }
}

// ---------------- 3) merge kernel: oh = (o0+o1)/(l0+l1), fp16 ----------------
__global__ void merge_kernel() {
    int idx = blockIdx.x * 256 + threadIdx.x;
    int row = idx >> 5;
    int u = idx & 31;
    int h = u >> 2;
    int b = row >> 12;
    int rloc = row & 4095;
    float l0 = g_l[((0 * NB + b) * NH + h) * LQ + rloc];
    float l1 = g_l[((1 * NB + b) * NH + h) * LQ + rloc];
    float inv = 1.f / (l0 + l1);
    size_t base = (size_t)row * CDIM + u * 8;
    uint4 a0 = *(const uint4*)(g_o0 + base);
    uint4 a1 = *(const uint4*)(g_o1 + base);
    uint4 r;
    unsigned* pa = (unsigned*)&a0;
    unsigned* pb = (unsigned*)&a1;
    unsigned* pr = (unsigned*)&r;
#pragma unroll
    for (int i = 0; i < 4; i++) {
        __half2 ha = *(__half2*)&pa[i];
        __half2 hb = *(__half2*)&pb[i];
        float lo = (__low2float(ha) + __low2float(hb)) * inv;
        float hi = (__high2float(ha) + __high2float(hb)) * inv;
        pr[i] = packhf(lo, hi);
    }
    *(uint4*)(g_oh + base) = r;
}

// ---------------- 4) output GEMM (BM=128): pipelined, + fold + src multiply ----------------
__global__ __launch_bounds__(256, 3) void gemm_out_kernel(const __half* __restrict__ A,
                                                          const __half* __restrict__ Wh,
                                                          const float* __restrict__ bias,
                                                          float* __restrict__ Cout,
                                                          const float* __restrict__ src) {
    int n0 = blockIdx.x * 64;
    int m0 = blockIdx.y * 128;
    int tid = threadIdx.x;
    GemmCtx c;
    gemm_init_ctx(c, tid);

    float acc[2][4][4] = {};
    gemm_mainloop(c, A, Wh, m0, n0, acc);

    float* Cs = (float*)dynsm;     // [128 rows][stride 68]
#pragma unroll
    for (int mi = 0; mi < 2; mi++)
#pragma unroll
        for (int rs = 0; rs < 2; rs++) {
            int rowl = c.wm + mi * 16 + c.g + rs * 8;
#pragma unroll
            for (int nj = 0; nj < 4; nj++) {
                int coll = c.wn + nj * 8 + 2 * c.t4;
                float2 v = make_float2(acc[mi][nj][rs * 2 + 0] + bias[n0 + coll],
                                       acc[mi][nj][rs * 2 + 1] + bias[n0 + coll + 1]);
                *(float2*)(Cs + rowl * 68 + coll) = v;
            }
        }
    __syncthreads();
    {
        int cc = tid & 63;
        int lb = (tid >> 6) * 32;
        int bb = m0 >> 12;
        int l0g = (m0 & 4095) + lb;
        size_t obase = (((size_t)(bb * CDIM + n0 + cc)) << 12) + l0g;
#pragma unroll
        for (int i = 0; i < 32; i += 4) {
            float4 s4 = *(const float4*)(src + obase + i);
            float4 r;
            r.x = Cs[(lb + i + 0) * 68 + cc] * s4.x;
            r.y = Cs[(lb + i + 1) * 68 + cc] * s4.y;
            r.z = Cs[(lb + i + 2) * 68 + cc] * s4.z;
            r.w = Cs[(lb + i + 3) * 68 + cc] * s4.w;
            *(float4*)(Cout + obase + i) = r;
        }
    }
}

// ---------------- launch ----------------
extern "C" void kernel_launch(void* const* d_in, const int* in_sizes, int n_in,
                              void* d_out, int out_size) {
    const float* feat = (const float*)d_in[0];
    const float* src  = (const float*)d_in[1];
    const float* Wq = (const float*)d_in[2];
    const float* bq = (const float*)d_in[3];
    const float* Wk = (const float*)d_in[4];
    const float* bk = (const float*)d_in[5];
    const float* Wv = (const float*)d_in[6];
    const float* bv = (const float*)d_in[7];
    const float* Wo = (const float*)d_in[8];
    const float* bo = (const float*)d_in[9];
    float* out = (float*)d_out;

    __half *p_qin, *p_kvin, *p_Wh, *p_oh;
    cudaGetSymbolAddress((void**)&p_qin,  g_qin_h);
    cudaGetSymbolAddress((void**)&p_kvin, g_kvin_h);
    cudaGetSymbolAddress((void**)&p_Wh,   g_Wh);
    cudaGetSymbolAddress((void**)&p_oh,   g_oh);

    static bool attr_done = false;
    if (!attr_done) {
        cudaFuncSetAttribute(gemm_qkv_kernel, cudaFuncAttributeMaxDynamicSharedMemorySize, GDSMEM);
        cudaFuncSetAttribute(gemm_out_kernel, cudaFuncAttributeMaxDynamicSharedMemorySize, GDSMEM);
        attr_done = true;
    }

    // 0) prep: transpose + gather + weight convert
    prep_kernel<<<2048 + 8192 + 256, 256>>>(src, feat, Wq, Wk, Wv, Wo);
    // 1) Q/K/V projections
    {
        dim3 grid(CDIM / 64, 3 * MTOT / 128);
        gemm_qkv_kernel<<<grid, 256, GDSMEM>>>(p_qin, p_kvin, p_Wh, bq, bk, bv);
    }
    // 2) attention (split-KV x2, one barrier per tile)
    {
        dim3 grid(LQ / 128, NH, NB * 2);
        flash_fp16_kernel<<<grid, 256>>>();
    }
    // 3) merge splits + normalize -> fp16 A
    merge_kernel<<<1024, 256>>>();
    // 4) output projection + fold + src multiply
    {
        dim3 grid(CDIM / 64, MTOT / 128);
        gemm_out_kernel<<<grid, 256, GDSMEM>>>(p_oh, p_Wh + 3 * CDIM * CDIM, bo, out, src);
    }
}

// round 17
// speedup vs baseline: 1.0082x; 1.0082x over previous
#include <cuda_runtime.h>
#include <cuda_fp16.h>
#include <cstdint>

#define LQ   4096
#define CDIM 256
#define NB   2
#define NH   8
#define MTOT 8192

// ---------------- scratch ----------------
__device__ __half g_qin_h [MTOT*CDIM];   // transposed src, fp16
__device__ __half g_kvin_h[MTOT*CDIM];   // gathered kv, fp16
__device__ __half g_qh    [MTOT*CDIM];   // Q fp16 (pre-scaled by 1/sqrt(d)*log2e)
__device__ __half g_kh    [MTOT*CDIM];   // K fp16 row-major
__device__ __half g_vt    [NB*CDIM*LQ];  // V fp16 transposed [b][c][kv]
__device__ __half g_o0    [MTOT*CDIM];   // unnormalized attention out fp16, split 0
__device__ __half g_o1    [MTOT*CDIM];   // split 1
__device__ __half g_oh    [MTOT*CDIM];   // merged+normalized attention out fp16
__device__ float  g_l     [2*NB*NH*LQ];  // softmax denominators [s][b][h][row]
__device__ __half g_Wh    [4*CDIM*CDIM]; // fp16 weights: q,k,v,o

// ---------------- helpers ----------------
__device__ __forceinline__ unsigned packhf(float lo, float hi) {
    unsigned d;
    asm("cvt.rn.f16x2.f32 %0, %1, %2;" : "=r"(d) : "f"(hi), "f"(lo));
    return d;
}
__device__ __forceinline__ unsigned h2ex2(unsigned x) {
    unsigned d;
    asm("ex2.approx.f16x2 %0, %1;" : "=r"(d) : "r"(x));
    return d;
}
__device__ __forceinline__ __half2 u2h(unsigned x) {
    __half2 h;
    *(unsigned*)&h = x;
    return h;
}
__device__ __forceinline__ unsigned h2u(__half2 h) {
    return *(unsigned*)&h;
}
__device__ __forceinline__ void mma_fp16(float c[4],
                                         unsigned a0, unsigned a1, unsigned a2, unsigned a3,
                                         unsigned b0, unsigned b1) {
    asm volatile(
        "mma.sync.aligned.m16n8k16.row.col.f32.f16.f16.f32 "
        "{%0,%1,%2,%3},{%4,%5,%6,%7},{%8,%9},{%0,%1,%2,%3};"
        : "+f"(c[0]), "+f"(c[1]), "+f"(c[2]), "+f"(c[3])
        : "r"(a0), "r"(a1), "r"(a2), "r"(a3), "r"(b0), "r"(b1));
}
__device__ __forceinline__ void ldsm4(unsigned& r0, unsigned& r1, unsigned& r2, unsigned& r3,
                                      unsigned addr) {
    asm volatile("ldmatrix.sync.aligned.m8n8.x4.shared.b16 {%0,%1,%2,%3}, [%4];"
                 : "=r"(r0), "=r"(r1), "=r"(r2), "=r"(r3) : "r"(addr));
}
__device__ __forceinline__ void cpa16(void* s, const void* g) {
    unsigned sa = (unsigned)__cvta_generic_to_shared(s);
    asm volatile("cp.async.cg.shared.global [%0], [%1], 16;" :: "r"(sa), "l"(g));
}

// ---------------- 0) merged prep: transpose src + gather kv + weight convert ----------------
__global__ void prep_kernel(const float* __restrict__ src, const float* __restrict__ feat,
                            const float* __restrict__ wq, const float* __restrict__ wk,
                            const float* __restrict__ wv, const float* __restrict__ wo) {
    __shared__ float tile[32][33];
    int bid = blockIdx.x;
    int tid = threadIdx.x;
    if (bid < 2048) {
        int x = tid & 31, y = tid >> 5;
        int l0 = (bid & 127) * 32;
        int c0 = ((bid >> 7) & 7) * 32;
        int b  = bid >> 10;
#pragma unroll
        for (int i = 0; i < 4; i++) {
            int c = c0 + y + i * 8;
            tile[y + i * 8][x] = src[((size_t)(b * CDIM + c) << 12) + (l0 + x)];
        }
        __syncthreads();
#pragma unroll
        for (int i = 0; i < 4; i++) {
            int l = l0 + y + i * 8;
            g_qin_h[((size_t)(b * LQ + l)) * CDIM + c0 + x] = __float2half(tile[x][y + i * 8]);
        }
    } else if (bid < 2048 + 8192) {
        int idx = (bid - 2048) * 256 + tid;
        int j = idx & 255;
        int l = (idx >> 8) & 4095;
        int b = idx >> 20;
        int c = j / 9;
        int k = j - c * 9;
        int kh = k / 3;
        int kw = k - kh * 3;
        int oh = l >> 6, ow = l & 63;
        int fh = 2 * oh + kh - 1;
        int fw = 2 * ow + kw - 1;
        float val = 0.f;
        if ((unsigned)fh < 128u && (unsigned)fw < 128u)
            val = feat[(((size_t)(b * CDIM + c)) << 14) + (fh << 7) + fw];
        g_kvin_h[idx] = __float2half(val);
    } else {
        int t = (bid - 2048 - 8192) * 256 + tid;
        int idx4 = t * 4;
        int m = idx4 >> 16;
        const float* s = (m == 0) ? wq : (m == 1) ? wk : (m == 2) ? wv : wo;
        float4 v = *(const float4*)(s + (idx4 & 65535));
        uint2 p;
        p.x = packhf(v.x, v.y);
        p.y = packhf(v.z, v.w);
        *(uint2*)(g_Wh + idx4) = p;
    }
}

// ---------------- BM=128 x BN=64 x BK=64 fp16 GEMM, 256 thr (8 warps), double-buffered (R15) ----------------
#define ASTR 36
#define QS (0.17677669529663687f * 1.4426950408889634f)
#define GD_A0 0
#define GD_A1 (128 * ASTR)
#define GD_W0 (2 * 128 * ASTR)
#define GD_W1 (2 * 128 * ASTR + 64 * ASTR)
#define GDSMEM ((2 * 128 + 2 * 64) * ASTR * 4)

extern __shared__ unsigned dynsm[];

struct GemmCtx {
    int wm, wn, g, t4;
    int ar, ah;
    int wr, wq;
};

__device__ __forceinline__ void gemm_mainloop(GemmCtx& c, const __half* A, const __half* Wh,
                                              int m0, int n0, float acc[2][4][4]) {
    const uint4* Ag = (const uint4*)(A + (size_t)(m0 + c.ar) * CDIM);
    const uint4* Wg = (const uint4*)(Wh + (size_t)(n0 + c.wr) * CDIM);
    unsigned* Ab[2] = { dynsm + GD_A0, dynsm + GD_A1 };
    unsigned* Wb[2] = { dynsm + GD_W0, dynsm + GD_W1 };
#define G_ISSUE(KT) do {                                                        \
        int bf_ = (KT) & 1;                                                     \
        _Pragma("unroll")                                                       \
        for (int i_ = 0; i_ < 4; i_++)                                          \
            cpa16(Ab[bf_] + c.ar * ASTR + (c.ah * 4 + i_) * 4, Ag + (KT) * 8 + c.ah * 4 + i_); \
        _Pragma("unroll")                                                       \
        for (int i_ = 0; i_ < 2; i_++)                                          \
            cpa16(Wb[bf_] + c.wr * ASTR + (c.wq * 2 + i_) * 4, Wg + (KT) * 8 + c.wq * 2 + i_); \
        asm volatile("cp.async.commit_group;");                                 \
    } while (0)
    G_ISSUE(0);
    for (int kt = 0; kt < 4; kt++) {
        if (kt < 3) {
            G_ISSUE(kt + 1);
            asm volatile("cp.async.wait_group 1;");
        } else {
            asm volatile("cp.async.wait_group 0;");
        }
        __syncthreads();
        const unsigned* Ah = Ab[kt & 1];
        const unsigned* Ws = Wb[kt & 1];
#pragma unroll
        for (int ks = 0; ks < 4; ks++) {
            unsigned av[2][4], bv2[4][2];
#pragma unroll
            for (int mi = 0; mi < 2; mi++) {
                int rb = (c.wm + mi * 16 + c.g) * ASTR + ks * 8;
                av[mi][0] = Ah[rb + c.t4];
                av[mi][1] = Ah[rb + 8 * ASTR + c.t4];
                av[mi][2] = Ah[rb + c.t4 + 4];
                av[mi][3] = Ah[rb + 8 * ASTR + c.t4 + 4];
            }
#pragma unroll
            for (int nj = 0; nj < 4; nj++) {
                int rb = (c.wn + nj * 8 + c.g) * ASTR + ks * 8;
                bv2[nj][0] = Ws[rb + c.t4];
                bv2[nj][1] = Ws[rb + c.t4 + 4];
            }
#pragma unroll
            for (int mi = 0; mi < 2; mi++)
#pragma unroll
                for (int nj = 0; nj < 4; nj++)
                    mma_fp16(acc[mi][nj], av[mi][0], av[mi][1], av[mi][2], av[mi][3],
                             bv2[nj][0], bv2[nj][1]);
        }
        __syncthreads();
    }
#undef G_ISSUE
}

__device__ __forceinline__ void gemm_init_ctx(GemmCtx& c, int tid) {
    int warp = tid >> 5, lane = tid & 31;
    c.g = lane >> 2; c.t4 = lane & 3;
    c.wm = (warp >> 1) * 32;
    c.wn = (warp & 1) * 32;
    c.ar = tid >> 1; c.ah = tid & 1;
    c.wr = tid >> 2; c.wq = tid & 3;
}

// ---------------- 1) merged Q/K/V fp16 GEMM (one launch, 768 blocks) ----------------
__global__ __launch_bounds__(256) void gemm_qkv_kernel(const __half* __restrict__ Aq,
                                                       const __half* __restrict__ Akv,
                                                       const __half* __restrict__ Whall,
                                                       const float* __restrict__ bq,
                                                       const float* __restrict__ bk,
                                                       const float* __restrict__ bv) {
    int mode = blockIdx.y >> 6;
    int m0 = (blockIdx.y & 63) * 128;
    int n0 = blockIdx.x * 64;
    const __half* A = (mode == 0) ? Aq : Akv;
    const __half* Wh = Whall + mode * CDIM * CDIM;
    const float* bias = (mode == 0) ? bq : (mode == 1) ? bk : bv;

    int tid = threadIdx.x;
    GemmCtx c;
    gemm_init_ctx(c, tid);

    float acc[2][4][4] = {};
    gemm_mainloop(c, A, Wh, m0, n0, acc);

    if (mode != 2) {
        __half* Cout = (mode == 0) ? g_qh : g_kh;
        float s = (mode == 0) ? QS : 1.f;
#pragma unroll
        for (int mi = 0; mi < 2; mi++)
#pragma unroll
            for (int rs = 0; rs < 2; rs++) {
                int row = m0 + c.wm + mi * 16 + c.g + rs * 8;
#pragma unroll
                for (int nj = 0; nj < 4; nj++) {
                    int col = n0 + c.wn + nj * 8 + 2 * c.t4;
                    float v0 = acc[mi][nj][rs * 2 + 0] + bias[col];
                    float v1 = acc[mi][nj][rs * 2 + 1] + bias[col + 1];
                    *(unsigned*)(Cout + (size_t)row * CDIM + col) = packhf(v0 * s, v1 * s);
                }
            }
    } else {
        __half* Ch = (__half*)dynsm;
        __syncthreads();
#pragma unroll
        for (int mi = 0; mi < 2; mi++)
#pragma unroll
            for (int rs = 0; rs < 2; rs++) {
                int rowl = c.wm + mi * 16 + c.g + rs * 8;
#pragma unroll
                for (int nj = 0; nj < 4; nj++) {
                    int coll = c.wn + nj * 8 + 2 * c.t4;
                    Ch[(coll)     * 136 + rowl] = __float2half(acc[mi][nj][rs * 2 + 0] + bias[n0 + coll]);
                    Ch[(coll + 1) * 136 + rowl] = __float2half(acc[mi][nj][rs * 2 + 1] + bias[n0 + coll + 1]);
                }
            }
        __syncthreads();
        {
            int cc = tid >> 2, qq = tid & 3;
            int b = m0 >> 12;
            int kv0 = m0 & 4095;
            uint4* dst = (uint4*)(g_vt + ((size_t)(b * CDIM + n0 + cc)) * LQ + kv0 + qq * 32);
            const uint4* s4 = (const uint4*)(Ch + cc * 136 + qq * 32);
#pragma unroll
            for (int i = 0; i < 4; i++) dst[i] = s4[i];
        }
    }
}

// ---------------- 2) flash attention: fp16, split-KV x2, one barrier/tile, fused lacc ----------------
#define FST 36
__global__ __launch_bounds__(256) void flash_fp16_kernel() {
    __shared__ unsigned Kt[2][64 * FST];
    __shared__ unsigned Vt[2][32 * FST];

    int qt = blockIdx.x, h = blockIdx.y;
    int b = blockIdx.z >> 1, s = blockIdx.z & 1;
    int tid = threadIdx.x;
    int w = tid >> 5, lane = tid & 31;
    int g = lane >> 2, t4 = lane & 3;
    int m0 = w * 16;
    int qbase = qt * 128;
    const unsigned ONES = 0x3C003C00u;

    unsigned qa[2][4];
    {
        const __half* Qp = g_qh + ((size_t)(b * LQ + qbase + m0)) * CDIM + h * 32;
#pragma unroll
        for (int kf = 0; kf < 2; kf++) {
            int cb = kf * 16 + 2 * t4;
            qa[kf][0] = *(const unsigned*)(Qp + (size_t)g * CDIM + cb);
            qa[kf][1] = *(const unsigned*)(Qp + (size_t)(g + 8) * CDIM + cb);
            qa[kf][2] = *(const unsigned*)(Qp + (size_t)g * CDIM + cb + 8);
            qa[kf][3] = *(const unsigned*)(Qp + (size_t)(g + 8) * CDIM + cb + 8);
        }
    }

    float oacc[4][4] = {};
    float lacc[4] = {};

    int kr = tid >> 2, kq = tid & 3;
    int vr = tid >> 3, vq = tid & 7;

    const uint4* kgp = (const uint4*)(g_kh + ((size_t)(b * LQ + kr)) * CDIM + h * 32);
    const uint4* vgp = (const uint4*)(g_vt + ((size_t)(b * CDIM + h * 32 + vr)) * LQ);
    int tbase = s * 32;

    unsigned ksh[2], vsh[2];
    ksh[0] = (unsigned)__cvta_generic_to_shared(&Kt[0][0]);
    ksh[1] = (unsigned)__cvta_generic_to_shared(&Kt[1][0]);
    vsh[0] = (unsigned)__cvta_generic_to_shared(&Vt[0][0]);
    vsh[1] = (unsigned)__cvta_generic_to_shared(&Vt[1][0]);
    unsigned koff = ((lane & 7) * FST + (lane >> 3) * 4) * 4;
    unsigned voff = koff;

#define ISSUE_TILE(T) do {                                                    \
        int buf_ = (T) & 1;                                                   \
        cpa16(&Kt[buf_][kr * FST + kq * 4], kgp + (size_t)(tbase + (T)) * 64 * (CDIM / 8) + kq); \
        cpa16(&Vt[buf_][vr * FST + vq * 4], vgp + (tbase + (T)) * 8 + vq);    \
        asm volatile("cp.async.commit_group;");                               \
    } while (0)

    ISSUE_TILE(0);

    for (int t = 0; t < 32; t++) {
        asm volatile("cp.async.wait_group 0;");
        __syncthreads();
        if (t < 31) ISSUE_TILE(t + 1);

        int buf = t & 1;
        unsigned kb = ksh[buf] + koff;
        unsigned vb = vsh[buf] + voff;

        // ---- S = Q K^T ----
        float sacc[8][4] = {};
#pragma unroll
        for (int j = 0; j < 8; j++) {
            unsigned r0, r1, r2, r3;
            ldsm4(r0, r1, r2, r3, kb + j * (8 * FST * 4));
            mma_fp16(sacc[j], qa[0][0], qa[0][1], qa[0][2], qa[0][3], r0, r1);
            mma_fp16(sacc[j], qa[1][0], qa[1][1], qa[1][2], qa[1][3], r2, r3);
        }

        // ---- P = exp2(S) ----
        unsigned pa[4][4];
#pragma unroll
        for (int kf = 0; kf < 4; kf++) {
            int j0 = 2 * kf, j1 = 2 * kf + 1;
            pa[kf][0] = h2ex2(packhf(sacc[j0][0], sacc[j0][1]));
            pa[kf][1] = h2ex2(packhf(sacc[j0][2], sacc[j0][3]));
            pa[kf][2] = h2ex2(packhf(sacc[j1][0], sacc[j1][1]));
            pa[kf][3] = h2ex2(packhf(sacc[j1][2], sacc[j1][3]));
        }

        // ---- row sums: merge the 4 kf A-fragments with HADD2 (FMA pipe),
        //      then ONE ones-mma (was 4). fp16 partial sums validated in R14. ----
        {
            unsigned sf0 = h2u(__hadd2(__hadd2(u2h(pa[0][0]), u2h(pa[1][0])),
                                       __hadd2(u2h(pa[2][0]), u2h(pa[3][0]))));
            unsigned sf1 = h2u(__hadd2(__hadd2(u2h(pa[0][1]), u2h(pa[1][1])),
                                       __hadd2(u2h(pa[2][1]), u2h(pa[3][1]))));
            unsigned sf2 = h2u(__hadd2(__hadd2(u2h(pa[0][2]), u2h(pa[1][2])),
                                       __hadd2(u2h(pa[2][2]), u2h(pa[3][2]))));
            unsigned sf3 = h2u(__hadd2(__hadd2(u2h(pa[0][3]), u2h(pa[1][3])),
                                       __hadd2(u2h(pa[2][3]), u2h(pa[3][3]))));
            mma_fp16(lacc, sf0, sf1, sf2, sf3, ONES, ONES);
        }

        // ---- O += P V ----
#pragma unroll
        for (int nn = 0; nn < 4; nn++) {
            unsigned v0, v1, v2, v3, v4, v5, v6, v7;
            unsigned a = vb + nn * (8 * FST * 4);
            ldsm4(v0, v1, v2, v3, a);
            ldsm4(v4, v5, v6, v7, a + 64);
            mma_fp16(oacc[nn], pa[0][0], pa[0][1], pa[0][2], pa[0][3], v0, v1);
            mma_fp16(oacc[nn], pa[1][0], pa[1][1], pa[1][2], pa[1][3], v2, v3);
            mma_fp16(oacc[nn], pa[2][0], pa[2][1], pa[2][2], pa[2][3], v4, v5);
            mma_fp16(oacc[nn], pa[3][0], pa[3][1], pa[3][2], pa[3][3], v6, v7);
        }
    }
#undef ISSUE_TILE

    __half* OB = s ? g_o1 : g_o0;
    __half* op = OB + ((size_t)(b * LQ + qbase + m0)) * CDIM + h * 32;
#pragma unroll
    for (int nn = 0; nn < 4; nn++) {
        *(unsigned*)(op + (size_t)g * CDIM + nn * 8 + 2 * t4) =
            packhf(oacc[nn][0], oacc[nn][1]);
        *(unsigned*)(op + (size_t)(g + 8) * CDIM + nn * 8 + 2 * t4) =
            packhf(oacc[nn][2], oacc[nn][3]);
    }
    if (t4 == 0) {
        int row = qbase + m0 + g;
        g_l[((s * NB + b) * NH + h) * LQ + row]     = lacc[0];
        g_l[((s * NB + b) * NH + h) * LQ + row + 8] = lacc[2];
    }
}

// ---------------- 3) merge kernel: oh = (o0+o1)/(l0+l1), fp16 ----------------
__global__ void merge_kernel() {
    int idx = blockIdx.x * 256 + threadIdx.x;
    int row = idx >> 5;
    int u = idx & 31;
    int h = u >> 2;
    int b = row >> 12;
    int rloc = row & 4095;
    float l0 = g_l[((0 * NB + b) * NH + h) * LQ + rloc];
    float l1 = g_l[((1 * NB + b) * NH + h) * LQ + rloc];
    float inv = 1.f / (l0 + l1);
    size_t base = (size_t)row * CDIM + u * 8;
    uint4 a0 = *(const uint4*)(g_o0 + base);
    uint4 a1 = *(const uint4*)(g_o1 + base);
    uint4 r;
    unsigned* pa = (unsigned*)&a0;
    unsigned* pb = (unsigned*)&a1;
    unsigned* pr = (unsigned*)&r;
#pragma unroll
    for (int i = 0; i < 4; i++) {
        __half2 ha = *(__half2*)&pa[i];
        __half2 hb = *(__half2*)&pb[i];
        float lo = (__low2float(ha) + __low2float(hb)) * inv;
        float hi = (__high2float(ha) + __high2float(hb)) * inv;
        pr[i] = packhf(lo, hi);
    }
    *(uint4*)(g_oh + base) = r;
}

// ---------------- 4) output GEMM (BM=128): pipelined, + fold + src multiply ----------------
__global__ __launch_bounds__(256) void gemm_out_kernel(const __half* __restrict__ A,
                                                       const __half* __restrict__ Wh,
                                                       const float* __restrict__ bias,
                                                       float* __restrict__ Cout,
                                                       const float* __restrict__ src) {
    int n0 = blockIdx.x * 64;
    int m0 = blockIdx.y * 128;
    int tid = threadIdx.x;
    GemmCtx c;
    gemm_init_ctx(c, tid);

    float acc[2][4][4] = {};
    gemm_mainloop(c, A, Wh, m0, n0, acc);

    float* Cs = (float*)dynsm;     // [128 rows][stride 68]
    __syncthreads();
#pragma unroll
    for (int mi = 0; mi < 2; mi++)
#pragma unroll
        for (int rs = 0; rs < 2; rs++) {
            int rowl = c.wm + mi * 16 + c.g + rs * 8;
#pragma unroll
            for (int nj = 0; nj < 4; nj++) {
                int coll = c.wn + nj * 8 + 2 * c.t4;
                float2 v = make_float2(acc[mi][nj][rs * 2 + 0] + bias[n0 + coll],
                                       acc[mi][nj][rs * 2 + 1] + bias[n0 + coll + 1]);
                *(float2*)(Cs + rowl * 68 + coll) = v;
            }
        }
    __syncthreads();
    {
        int cc = tid & 63;
        int lb = (tid >> 6) * 32;
        int bb = m0 >> 12;
        int l0g = (m0 & 4095) + lb;
        size_t obase = (((size_t)(bb * CDIM + n0 + cc)) << 12) + l0g;
#pragma unroll
        for (int i = 0; i < 32; i += 4) {
            float4 s4 = *(const float4*)(src + obase + i);
            float4 r;
            r.x = Cs[(lb + i + 0) * 68 + cc] * s4.x;
            r.y = Cs[(lb + i + 1) * 68 + cc] * s4.y;
            r.z = Cs[(lb + i + 2) * 68 + cc] * s4.z;
            r.w = Cs[(lb + i + 3) * 68 + cc] * s4.w;
            *(float4*)(Cout + obase + i) = r;
        }
    }
}

// ---------------- launch ----------------
extern "C" void kernel_launch(void* const* d_in, const int* in_sizes, int n_in,
                              void* d_out, int out_size) {
    const float* feat = (const float*)d_in[0];
    const float* src  = (const float*)d_in[1];
    const float* Wq = (const float*)d_in[2];
    const float* bq = (const float*)d_in[3];
    const float* Wk = (const float*)d_in[4];
    const float* bk = (const float*)d_in[5];
    const float* Wv = (const float*)d_in[6];
    const float* bv = (const float*)d_in[7];
    const float* Wo = (const float*)d_in[8];
    const float* bo = (const float*)d_in[9];
    float* out = (float*)d_out;

    __half *p_qin, *p_kvin, *p_Wh, *p_oh;
    cudaGetSymbolAddress((void**)&p_qin,  g_qin_h);
    cudaGetSymbolAddress((void**)&p_kvin, g_kvin_h);
    cudaGetSymbolAddress((void**)&p_Wh,   g_Wh);
    cudaGetSymbolAddress((void**)&p_oh,   g_oh);

    static bool attr_done = false;
    if (!attr_done) {
        cudaFuncSetAttribute(gemm_qkv_kernel, cudaFuncAttributeMaxDynamicSharedMemorySize, GDSMEM);
        cudaFuncSetAttribute(gemm_out_kernel, cudaFuncAttributeMaxDynamicSharedMemorySize, GDSMEM);
        attr_done = true;
    }

    // 0) prep: transpose + gather + weight convert
    prep_kernel<<<2048 + 8192 + 256, 256>>>(src, feat, Wq, Wk, Wv, Wo);
    // 1) Q/K/V projections
    {
        dim3 grid(CDIM / 64, 3 * MTOT / 128);
        gemm_qkv_kernel<<<grid, 256, GDSMEM>>>(p_qin, p_kvin, p_Wh, bq, bk, bv);
    }
    // 2) attention (split-KV x2, one barrier per tile, fused lacc)
    {
        dim3 grid(LQ / 128, NH, NB * 2);
        flash_fp16_kernel<<<grid, 256>>>();
    }
    // 3) merge splits + normalize -> fp16 A
    merge_kernel<<<1024, 256>>>();
    // 4) output projection + fold + src multiply
    {
        dim3 grid(CDIM / 64, MTOT / 128);
        gemm_out_kernel<<<grid, 256, GDSMEM>>>(p_oh, p_Wh + 3 * CDIM * CDIM, bo, out, src);
    }
}